// round 1
// baseline (speedup 1.0000x reference)
#include <cuda_runtime.h>

// ---------------------------------------------------------------------------
// BenesBlock: 25 switch-unit steps on [8192, 512] fp32.
// Per step: v=[4096,1024]; h = v@w1 [4096,2048]; per-COLUMN (axis-0) LN;
// leaky_relu(0.2); cand = h@w2 + b2 -> [8192,512];
// y = sigmoid(rs)*x + cand*CW; then closed-form shuffle permutation.
// Steps 0-11: weights f, scatter dst=ROL[j]; 12-23: weights r, scatter ROR[j];
// step 24: weights m, no permutation, writes d_out.
// ---------------------------------------------------------------------------

#define L    8192
#define NU   512
#define M_   4096      // L/2
#define K1   1024      // 2*NU
#define N1   2048      // 4*NU
#define K2   2048
#define N2   1024
#define CW_F 0.10897247358851683f   // sqrt(1-0.9^2)*0.25
#define EPS_F 1e-6f

#define BM 128
#define BN 128
#define BK 16
#define TM 8
#define TN 8

// Scratch (static device globals — no allocation allowed).
__device__ float g_y[2][L * NU];          // ping-pong activations (2 x 16MB)
__device__ float g_h[M_ * N1];            // GEMM1 output (32MB)
__device__ float g_part[8][2 * N1];       // deterministic partial col sums
__device__ float g_stats[2 * N1];         // (mean, rstd) interleaved per column
__device__ float g_sig[3 * NU];           // sigmoid(rs) for f/r/m

// ---------------------------------------------------------------------------
__global__ void copy_x_kernel(const float* __restrict__ x) {
    int i = blockIdx.x * blockDim.x + threadIdx.x;   // float4 index
    const float4* src = (const float4*)x;
    float4* dst = (float4*)g_y[0];
    if (i < (L * NU) / 4) dst[i] = src[i];
}

__global__ void sig_kernel(const float* __restrict__ rs_f,
                           const float* __restrict__ rs_r,
                           const float* __restrict__ rs_m) {
    int i = blockIdx.x * blockDim.x + threadIdx.x;
    if (i >= 3 * NU) return;
    const float* src = (i < NU) ? rs_f : (i < 2 * NU) ? rs_r : rs_m;
    float v = src[i & (NU - 1)];
    g_sig[i] = 1.0f / (1.0f + expf(-v));
}

// ---------------------------------------------------------------------------
// GEMM1: h = v @ w1.  A = g_y[cur] viewed [4096,1024], B = w1 [1024,2048].
__global__ __launch_bounds__(256) void gemm1_kernel(int cur, const float* __restrict__ w1) {
    __shared__ float As[BK][BM + 4];
    __shared__ float Bs[BK][BN];
    const float* __restrict__ A = g_y[cur];

    const int tid = threadIdx.x;
    const int tx = tid & 15, ty = tid >> 4;
    const int m0 = blockIdx.y * BM, n0 = blockIdx.x * BN;

    const int aRow = tid >> 2;          // 0..63
    const int aCol = (tid & 3) * 4;     // 0,4,8,12
    const int bRow = tid >> 5;          // 0..7
    const int bCol = (tid & 31) * 4;

    float acc[TM][TN];
#pragma unroll
    for (int i = 0; i < TM; i++)
#pragma unroll
        for (int j = 0; j < TN; j++) acc[i][j] = 0.f;

    for (int k0 = 0; k0 < K1; k0 += BK) {
#pragma unroll
        for (int p = 0; p < 2; p++) {
            int m = aRow + p * 64;
            float4 v = *(const float4*)&A[(size_t)(m0 + m) * K1 + k0 + aCol];
            As[aCol + 0][m] = v.x; As[aCol + 1][m] = v.y;
            As[aCol + 2][m] = v.z; As[aCol + 3][m] = v.w;
        }
#pragma unroll
        for (int p = 0; p < 2; p++) {
            int kk = bRow + p * 8;
            *(float4*)&Bs[kk][bCol] =
                *(const float4*)&w1[(size_t)(k0 + kk) * N1 + n0 + bCol];
        }
        __syncthreads();
#pragma unroll
        for (int kk = 0; kk < BK; kk++) {
            float a[TM], b[TN];
#pragma unroll
            for (int i = 0; i < TM; i++) a[i] = As[kk][ty * TM + i];
#pragma unroll
            for (int j = 0; j < TN; j++) b[j] = Bs[kk][tx * TN + j];
#pragma unroll
            for (int i = 0; i < TM; i++)
#pragma unroll
                for (int j = 0; j < TN; j++) acc[i][j] = fmaf(a[i], b[j], acc[i][j]);
        }
        __syncthreads();
    }
#pragma unroll
    for (int i = 0; i < TM; i++) {
        int r = m0 + ty * TM + i;
#pragma unroll
        for (int j = 0; j < TN; j += 4) {
            float4 v = make_float4(acc[i][j], acc[i][j + 1], acc[i][j + 2], acc[i][j + 3]);
            *(float4*)&g_h[(size_t)r * N1 + n0 + tx * TN + j] = v;
        }
    }
}

// ---------------------------------------------------------------------------
// Column stats of h over 4096 rows (deterministic, two-stage, no atomics).
__global__ void stats_partial_kernel() {   // grid (64, 8), block (32, 8)
    int col = blockIdx.x * 32 + threadIdx.x;
    int rg = blockIdx.y;
    float s = 0.f, q = 0.f;
    for (int r = rg * 512 + threadIdx.y; r < (rg + 1) * 512; r += 8) {
        float v = g_h[(size_t)r * N1 + col];
        s += v; q += v * v;
    }
    __shared__ float sh[2][8][32];
    sh[0][threadIdx.y][threadIdx.x] = s;
    sh[1][threadIdx.y][threadIdx.x] = q;
    __syncthreads();
    if (threadIdx.y == 0) {
        float S = 0.f, Q = 0.f;
#pragma unroll
        for (int t = 0; t < 8; t++) { S += sh[0][t][threadIdx.x]; Q += sh[1][t][threadIdx.x]; }
        g_part[rg][2 * col] = S;
        g_part[rg][2 * col + 1] = Q;
    }
}

__global__ void stats_final_kernel() {     // grid 8, block 256
    int c = blockIdx.x * 256 + threadIdx.x;
    if (c >= N1) return;
    float s = 0.f, q = 0.f;
#pragma unroll
    for (int rg = 0; rg < 8; rg++) { s += g_part[rg][2 * c]; q += g_part[rg][2 * c + 1]; }
    float mean = s * (1.0f / M_);
    float var = q * (1.0f / M_) - mean * mean;     // E[(h-mean)^2]
    g_stats[2 * c] = mean;
    g_stats[2 * c + 1] = rsqrtf(var + EPS_F);
}

// ---------------------------------------------------------------------------
// GEMM2: cand = lrelu(LN(h)) @ w2 + b2, fused residual + permutation scatter.
// dir: 0 = scatter ROL (forward), 1 = scatter ROR (reverse), 2 = identity.
__global__ __launch_bounds__(256) void gemm2_kernel(const float* __restrict__ w2,
                                                    const float* __restrict__ b2,
                                                    int stage, int dir, int cur,
                                                    float* __restrict__ dext) {
    __shared__ float As[BK][BM + 4];
    __shared__ float Bs[BK][BN];

    const int tid = threadIdx.x;
    const int tx = tid & 15, ty = tid >> 4;
    const int m0 = blockIdx.y * BM, n0 = blockIdx.x * BN;

    const int aRow = tid >> 2;
    const int aCol = (tid & 3) * 4;
    const int bRow = tid >> 5;
    const int bCol = (tid & 31) * 4;

    float acc[TM][TN];
#pragma unroll
    for (int i = 0; i < TM; i++)
#pragma unroll
        for (int j = 0; j < TN; j++) acc[i][j] = 0.f;

    for (int k0 = 0; k0 < K2; k0 += BK) {
        int kg = k0 + aCol;
        float4 sa = *(const float4*)&g_stats[2 * kg];       // mean k, rstd k, mean k+1, rstd k+1
        float4 sb = *(const float4*)&g_stats[2 * kg + 4];
#pragma unroll
        for (int p = 0; p < 2; p++) {
            int m = aRow + p * 64;
            float4 v = *(const float4*)&g_h[(size_t)(m0 + m) * K2 + kg];
            v.x = (v.x - sa.x) * sa.y;
            v.y = (v.y - sa.z) * sa.w;
            v.z = (v.z - sb.x) * sb.y;
            v.w = (v.w - sb.z) * sb.w;
            v.x = v.x > 0.f ? v.x : 0.2f * v.x;
            v.y = v.y > 0.f ? v.y : 0.2f * v.y;
            v.z = v.z > 0.f ? v.z : 0.2f * v.z;
            v.w = v.w > 0.f ? v.w : 0.2f * v.w;
            As[aCol + 0][m] = v.x; As[aCol + 1][m] = v.y;
            As[aCol + 2][m] = v.z; As[aCol + 3][m] = v.w;
        }
#pragma unroll
        for (int p = 0; p < 2; p++) {
            int kk = bRow + p * 8;
            *(float4*)&Bs[kk][bCol] =
                *(const float4*)&w2[(size_t)(k0 + kk) * N2 + n0 + bCol];
        }
        __syncthreads();
#pragma unroll
        for (int kk = 0; kk < BK; kk++) {
            float a[TM], b[TN];
#pragma unroll
            for (int i = 0; i < TM; i++) a[i] = As[kk][ty * TM + i];
#pragma unroll
            for (int j = 0; j < TN; j++) b[j] = Bs[kk][tx * TN + j];
#pragma unroll
            for (int i = 0; i < TM; i++)
#pragma unroll
                for (int j = 0; j < TN; j++) acc[i][j] = fmaf(a[i], b[j], acc[i][j]);
        }
        __syncthreads();
    }

    float* yout = dext ? dext : g_y[cur ^ 1];
    const float* ycur = g_y[cur];
#pragma unroll
    for (int i = 0; i < TM; i++) {
        int r = m0 + ty * TM + i;
#pragma unroll
        for (int j = 0; j < TN; j++) {
            int n = n0 + tx * TN + j;
            float cand = acc[i][j] + b2[n];
            int c = n & (NU - 1);
            int rowY = 2 * r + (n >> 9);
            float val = g_sig[stage * NU + c] * ycur[(size_t)r * 1024 + n] + cand * CW_F;
            int dst;
            if (dir == 0)       dst = (rowY < M_) ? (2 * rowY) : (2 * rowY - L + 1);
            else if (dir == 1)  dst = (rowY & 1) ? (M_ + (rowY >> 1)) : (rowY >> 1);
            else                dst = rowY;
            yout[(size_t)dst * NU + c] = val;
        }
    }
}

// ---------------------------------------------------------------------------
extern "C" void kernel_launch(void* const* d_in, const int* in_sizes, int n_in,
                              void* d_out, int out_size) {
    const float* x = (const float*)d_in[0];
    const float* rs[3] = {(const float*)d_in[1], (const float*)d_in[5], (const float*)d_in[9]};
    const float* w1[3] = {(const float*)d_in[2], (const float*)d_in[6], (const float*)d_in[10]};
    const float* w2[3] = {(const float*)d_in[3], (const float*)d_in[7], (const float*)d_in[11]};
    const float* b2[3] = {(const float*)d_in[4], (const float*)d_in[8], (const float*)d_in[12]};
    float* out = (float*)d_out;

    copy_x_kernel<<<(L * NU / 4 + 255) / 256, 256>>>(x);
    sig_kernel<<<6, 256>>>(rs[0], rs[1], rs[2]);

    dim3 blk(256);
    dim3 g1(N1 / BN, M_ / BM);   // (16, 32)
    dim3 g2(N2 / BN, M_ / BM);   // (8, 32)

    int cur = 0;
    for (int step = 0; step < 25; step++) {
        int stage = (step < 12) ? 0 : (step < 24) ? 1 : 2;
        int dir = stage;  // 0: scatter ROL, 1: scatter ROR, 2: identity
        gemm1_kernel<<<g1, blk>>>(cur, w1[stage]);
        stats_partial_kernel<<<dim3(64, 8), dim3(32, 8)>>>();
        stats_final_kernel<<<8, 256>>>();
        gemm2_kernel<<<g2, blk>>>(w2[stage], b2[stage], stage, dir, cur,
                                  (step == 24) ? out : nullptr);
        cur ^= 1;
    }
}